// round 1
// baseline (speedup 1.0000x reference)
#include <cuda_runtime.h>

#define BB 4
#define HH 512
#define WW 512
#define NPIX (BB*HH*WW)          // 1048576
#define T1 17                    // T_MAX + 1
#define CCL_ITERS 128

#define NF 1048576.0f
// float-rounded constants matching JAX weak-type promotion (double -> f32 at op)
#define SP0F ((float)0.6931471805599453)
#define C1F  ((float)(1.3132616875182228 - 0.6931471805599453))   // SP1 - SP0
#define C2F  ((float)(0.7310585786300049 - 0.5))                  // S1 - 0.5

// ---------------- device scratch (static, no allocation) ----------------
__device__ __align__(16) int g_lab0[NPIX];
__device__ __align__(16) int g_lab1[NPIX];
__device__ int g_inter[(size_t)NPIX * T1];   // confusion counts [comp][t]
__device__ int g_cnt_p[NPIX];                // predicted component sizes
__device__ unsigned char g_used[NPIX];       // matched flag per comp id
__device__ int g_cnt_t[T1];                  // target label histogram
__device__ float g_bce_sum, g_p_sum, g_pt_sum, g_t_sum;
__device__ float g_acc, g_matched, g_untgt;
__device__ int g_npred;
__device__ unsigned long long g_minkey;

// ---------------- reduction helpers ----------------
__device__ __forceinline__ float4 blockReduceSum4(float4 v) {
    __shared__ float4 s[8];
    unsigned m = 0xFFFFFFFFu;
    #pragma unroll
    for (int o = 16; o; o >>= 1) {
        v.x += __shfl_down_sync(m, v.x, o);
        v.y += __shfl_down_sync(m, v.y, o);
        v.z += __shfl_down_sync(m, v.z, o);
        v.w += __shfl_down_sync(m, v.w, o);
    }
    int lane = threadIdx.x & 31, wid = threadIdx.x >> 5;
    if (lane == 0) s[wid] = v;
    __syncthreads();
    if (wid == 0) {
        v = (lane < (blockDim.x >> 5)) ? s[lane] : make_float4(0.f, 0.f, 0.f, 0.f);
        #pragma unroll
        for (int o = 4; o; o >>= 1) {
            v.x += __shfl_down_sync(m, v.x, o);
            v.y += __shfl_down_sync(m, v.y, o);
            v.z += __shfl_down_sync(m, v.z, o);
            v.w += __shfl_down_sync(m, v.w, o);
        }
    }
    return v;
}

__device__ __forceinline__ int blockReduceSumI(int v) {
    __shared__ int s[8];
    unsigned m = 0xFFFFFFFFu;
    #pragma unroll
    for (int o = 16; o; o >>= 1) v += __shfl_down_sync(m, v, o);
    int lane = threadIdx.x & 31, wid = threadIdx.x >> 5;
    if (lane == 0) s[wid] = v;
    __syncthreads();
    if (wid == 0) {
        v = (lane < (blockDim.x >> 5)) ? s[lane] : 0;
        #pragma unroll
        for (int o = 4; o; o >>= 1) v += __shfl_down_sync(m, v, o);
    }
    return v;
}

__device__ __forceinline__ unsigned long long blockReduceMinU64(unsigned long long v) {
    __shared__ unsigned long long s[8];
    unsigned m = 0xFFFFFFFFu;
    #pragma unroll
    for (int o = 16; o; o >>= 1) {
        unsigned long long o2 = __shfl_down_sync(m, v, o);
        v = (o2 < v) ? o2 : v;
    }
    int lane = threadIdx.x & 31, wid = threadIdx.x >> 5;
    if (lane == 0) s[wid] = v;
    __syncthreads();
    if (wid == 0) {
        v = (lane < (blockDim.x >> 5)) ? s[lane] : ~0ULL;
        #pragma unroll
        for (int o = 4; o; o >>= 1) {
            unsigned long long o2 = __shfl_down_sync(m, v, o);
            v = (o2 < v) ? o2 : v;
        }
    }
    return v;
}

// ---------------- kernels ----------------
__global__ void init_kernel() {
    int t = threadIdx.x;
    if (t < T1) g_cnt_t[t] = 0;
    if (t == 0) {
        g_bce_sum = 0.f; g_p_sum = 0.f; g_pt_sum = 0.f; g_t_sum = 0.f;
        g_acc = 0.f; g_matched = 0.f; g_untgt = 0.f;
        g_npred = 0;
        g_minkey = ~0ULL;
    }
}

__global__ void zero_kernel() {
    size_t i = (size_t)blockIdx.x * blockDim.x + threadIdx.x;
    size_t stride = (size_t)gridDim.x * blockDim.x;
    const size_t tot = (size_t)NPIX * T1;
    for (size_t j = i; j < tot; j += stride) g_inter[j] = 0;
    for (size_t j = i; j < (size_t)NPIX; j += stride) { g_cnt_p[j] = 0; g_used[j] = 0; }
}

// fg decision + label init + base BCE/Dice partial sums + target histogram
__global__ void base_kernel(const float* __restrict__ pred, const int* __restrict__ tgt) {
    __shared__ int sbins[T1];
    if (threadIdx.x < T1) sbins[threadIdx.x] = 0;
    __syncthreads();

    int i = blockIdx.x * blockDim.x + threadIdx.x;   // grid = NPIX/256
    int b = i >> 18;                                  // H*W = 2^18
    int hw = i & ((1 << 18) - 1);
    const float* basep = pred + (size_t)b * 2 * HH * WW;
    float p0 = basep[hw];
    float p1 = basep[HH * WW + hw];
    bool fg = p1 > p0;                                // argmax with first-index tie

    int t = tgt[i];
    atomicAdd(&sbins[t], 1);

    float l = fg ? p1 : 0.0f;
    float y = (t > 0) ? 1.0f : 0.0f;
    float sp = fmaxf(l, 0.0f) + log1pf(expf(-fabsf(l)));   // softplus
    float p = 1.0f / (1.0f + expf(-l));                    // sigmoid

    g_lab0[i] = fg ? (i + 1) : 0;

    float4 v = make_float4(sp - l * y, p, p * y, y);
    v = blockReduceSum4(v);            // contains a __syncthreads (fences sbins too)
    if (threadIdx.x == 0) {
        atomicAdd(&g_bce_sum, v.x);
        atomicAdd(&g_p_sum,   v.y);
        atomicAdd(&g_pt_sum,  v.z);
        atomicAdd(&g_t_sum,   v.w);
    }
    if (threadIdx.x < T1) atomicAdd(&g_cnt_t[threadIdx.x], sbins[threadIdx.x]);
}

// one Jacobi max-propagation step, vectorized 4 px/thread (W=512 -> 128 quads/row)
__global__ void ccl_step(int dir) {
    const int* __restrict__ src = dir ? g_lab1 : g_lab0;
    int* __restrict__ dst = dir ? g_lab0 : g_lab1;

    int q = blockIdx.x * blockDim.x + threadIdx.x;    // grid = NPIX/4/256
    int i = q << 2;
    int w = i & (WW - 1);
    int h = (i >> 9) & (HH - 1);

    int4 c = reinterpret_cast<const int4*>(src)[q];
    int4 up = make_int4(0, 0, 0, 0), dn = make_int4(0, 0, 0, 0);
    if (h > 0)      up = reinterpret_cast<const int4*>(src)[q - (WW >> 2)];
    if (h < HH - 1) dn = reinterpret_cast<const int4*>(src)[q + (WW >> 2)];
    int lf = (w > 0)          ? src[i - 1] : 0;
    int rt = (w + 4 < WW)     ? src[i + 4] : 0;

    int4 r;
    r.x = c.x ? max(max(c.x, max(up.x, dn.x)), max(lf,  c.y)) : 0;
    r.y = c.y ? max(max(c.y, max(up.y, dn.y)), max(c.x, c.z)) : 0;
    r.z = c.z ? max(max(c.z, max(up.z, dn.z)), max(c.y, c.w)) : 0;
    r.w = c.w ? max(max(c.w, max(up.w, dn.w)), max(c.z, rt )) : 0;
    reinterpret_cast<int4*>(dst)[q] = r;
}

// build confusion counts via atomics (final labels are in g_lab0)
__global__ void build_kernel(const int* __restrict__ tgt) {
    int i = blockIdx.x * blockDim.x + threadIdx.x;
    int lab = g_lab0[i];
    if (lab) {
        int c = lab - 1;
        int t = tgt[i];
        atomicAdd(&g_inter[(size_t)c * T1 + t], 1);
        atomicAdd(&g_cnt_p[c], 1);
    }
}

__global__ void npred_kernel() {
    int i = blockIdx.x * blockDim.x + threadIdx.x;
    int stride = gridDim.x * blockDim.x;
    int c = 0;
    for (int j = i; j < NPIX; j += stride) c += (g_cnt_p[j] > 0);
    c = blockReduceSumI(c);
    if (threadIdx.x == 0) atomicAdd(&g_npred, c);
}

// lexicographic argmin over (loss, comp_id); loss > 0 always so bit-pack is monotone
__global__ void argmin_kernel(int t) {
    int i = blockIdx.x * blockDim.x + threadIdx.x;
    int stride = gridDim.x * blockDim.x;
    float ct = (float)g_cnt_t[t];
    unsigned long long best = ~0ULL;
    for (int c = i; c < NPIX; c += stride) {
        int cp = g_cnt_p[c];
        if (cp > 0 && !g_used[c]) {
            float cnt_p = (float)cp;
            float it = (float)g_inter[(size_t)c * T1 + t];
            float bce = (NF * SP0F + cnt_p * C1F - it) / NF;
            float sum_pt = 0.5f * ct + C2F * it;
            float sum_p  = 0.5f * NF + C2F * cnt_p;
            float dice = 1.0f - (2.0f * sum_pt + 1.0f) / ((sum_p + ct) + 1.0f);
            float loss = bce + dice;
            unsigned long long key =
                ((unsigned long long)__float_as_uint(loss) << 32) | (unsigned)c;
            best = (key < best) ? key : best;
        }
    }
    best = blockReduceMinU64(best);
    if (threadIdx.x == 0) atomicMin(&g_minkey, best);
}

__global__ void apply_kernel(int t) {
    int ct = g_cnt_t[t];
    unsigned long long key = g_minkey;
    bool present = ct > 0;
    bool any_avail = key != ~0ULL;
    if (present && any_avail) {
        float loss = __uint_as_float((unsigned)(key >> 32));
        g_acc += loss;
        g_used[(unsigned)(key & 0xFFFFFFFFu)] = 1;
        g_matched += 1.0f;
    } else if (present) {
        g_untgt += 1.0f;
    }
    g_minkey = ~0ULL;
}

__global__ void final_kernel(float* __restrict__ out) {
    float bce = g_bce_sum / NF;
    float dice = 1.0f - (2.0f * g_pt_sum + 1.0f) / ((g_p_sum + g_t_sum) + 1.0f);
    float res = bce + dice;
    out[0] = res + g_acc + ((float)g_npred - g_matched) + g_untgt;
}

// ---------------- launch ----------------
extern "C" void kernel_launch(void* const* d_in, const int* in_sizes, int n_in,
                              void* d_out, int out_size) {
    const float* pred = (const float*)d_in[0];   // [4,2,512,512] f32
    const int*   tgt  = (const int*)d_in[1];     // [4,1,512,512] i32
    float* out = (float*)d_out;

    init_kernel<<<1, 32>>>();
    zero_kernel<<<2048, 256>>>();
    base_kernel<<<NPIX / 256, 256>>>(pred, tgt);

    for (int k = 0; k < CCL_ITERS; k++)
        ccl_step<<<NPIX / 4 / 256, 256>>>(k & 1);   // ends with result in g_lab0

    build_kernel<<<NPIX / 256, 256>>>(tgt);
    npred_kernel<<<1024, 256>>>();

    for (int t = 1; t < T1; t++) {
        argmin_kernel<<<1024, 256>>>(t);
        apply_kernel<<<1, 1>>>(t);
    }
    final_kernel<<<1, 1>>>(out);
}

// round 2
// speedup vs baseline: 2.8878x; 2.8878x over previous
#include <cuda_runtime.h>

#define BB 4
#define HH 512
#define WW 512
#define NPIX (BB*HH*WW)          // 1048576
#define T1 17                    // T_MAX + 1
#define CAP (NPIX/2 + 64)        // max possible component count (checkerboard)

#define NF 1048576.0f
#define SP0F ((float)0.6931471805599453)
#define C1F  ((float)(1.3132616875182228 - 0.6931471805599453))   // SP1 - SP0
#define C2F  ((float)(0.7310585786300049 - 0.5))                  // S1 - 0.5

// ---------------- device scratch (static, no allocation) ----------------
__device__ int g_par[NPIX];                   // union-find parent; -1 = background
__device__ int g_cidx[NPIX];                  // root pixel -> compact component idx
__device__ int g_orig[CAP];                   // compact idx -> root pixel (orig id)
__device__ int g_cnt_c[CAP];                  // compact component sizes
__device__ unsigned char g_used[CAP];         // matched flag (compact)
__device__ int g_interc[(size_t)CAP * T1];    // compact confusion counts
__device__ int g_cnt_t[T1];                   // target label histogram
__device__ int g_m;                           // number of components
__device__ float g_bce_sum, g_p_sum, g_pt_sum, g_t_sum;
__device__ float g_acc, g_matched, g_untgt;
__device__ unsigned long long g_minkey;

// ---------------- helpers ----------------
__device__ __forceinline__ int uf_find(int x) {
    int p = g_par[x];
    while (p != x) { x = p; p = g_par[x]; }
    return x;
}

// union with root = MAX index (Komura-style, mirrored to max)
__device__ __forceinline__ void uf_unite(int a, int b) {
    while (true) {
        a = uf_find(a);
        b = uf_find(b);
        if (a == b) return;
        if (a > b) { int t = a; a = b; b = t; }   // a < b: attach a under b
        int old = atomicMax(&g_par[a], b);
        if (old == a) return;                     // a was root, now linked
        a = old;                                  // retry: unite old with b
    }
}

__device__ __forceinline__ float4 blockReduceSum4(float4 v) {
    __shared__ float4 s[8];
    unsigned m = 0xFFFFFFFFu;
    #pragma unroll
    for (int o = 16; o; o >>= 1) {
        v.x += __shfl_down_sync(m, v.x, o);
        v.y += __shfl_down_sync(m, v.y, o);
        v.z += __shfl_down_sync(m, v.z, o);
        v.w += __shfl_down_sync(m, v.w, o);
    }
    int lane = threadIdx.x & 31, wid = threadIdx.x >> 5;
    if (lane == 0) s[wid] = v;
    __syncthreads();
    if (wid == 0) {
        v = (lane < (blockDim.x >> 5)) ? s[lane] : make_float4(0.f, 0.f, 0.f, 0.f);
        #pragma unroll
        for (int o = 4; o; o >>= 1) {
            v.x += __shfl_down_sync(m, v.x, o);
            v.y += __shfl_down_sync(m, v.y, o);
            v.z += __shfl_down_sync(m, v.z, o);
            v.w += __shfl_down_sync(m, v.w, o);
        }
    }
    return v;
}

__device__ __forceinline__ unsigned long long blockReduceMinU64(unsigned long long v) {
    __shared__ unsigned long long s[8];
    unsigned m = 0xFFFFFFFFu;
    #pragma unroll
    for (int o = 16; o; o >>= 1) {
        unsigned long long o2 = __shfl_down_sync(m, v, o);
        v = (o2 < v) ? o2 : v;
    }
    int lane = threadIdx.x & 31, wid = threadIdx.x >> 5;
    if (lane == 0) s[wid] = v;
    __syncthreads();
    if (wid == 0) {
        v = (lane < (blockDim.x >> 5)) ? s[lane] : ~0ULL;
        #pragma unroll
        for (int o = 4; o; o >>= 1) {
            unsigned long long o2 = __shfl_down_sync(m, v, o);
            v = (o2 < v) ? o2 : v;
        }
    }
    return v;
}

// ---------------- kernels ----------------
__global__ void init_kernel() {
    int t = threadIdx.x;
    if (t < T1) g_cnt_t[t] = 0;
    if (t == 0) {
        g_bce_sum = 0.f; g_p_sum = 0.f; g_pt_sum = 0.f; g_t_sum = 0.f;
        g_acc = 0.f; g_matched = 0.f; g_untgt = 0.f;
        g_m = 0;
        g_minkey = ~0ULL;
    }
}

// fg decision + union-find init + base BCE/Dice partials + target histogram
__global__ void base_kernel(const float* __restrict__ pred, const int* __restrict__ tgt) {
    __shared__ int sbins[T1];
    if (threadIdx.x < T1) sbins[threadIdx.x] = 0;
    __syncthreads();

    int i = blockIdx.x * blockDim.x + threadIdx.x;
    int b = i >> 18;
    int hw = i & ((1 << 18) - 1);
    const float* basep = pred + (size_t)b * 2 * HH * WW;
    float p0 = basep[hw];
    float p1 = basep[HH * WW + hw];
    bool fg = p1 > p0;                          // argmax, first-index tie -> 0

    int t = tgt[i];
    atomicAdd(&sbins[t], 1);

    float l = fg ? p1 : 0.0f;
    float y = (t > 0) ? 1.0f : 0.0f;
    float sp = fmaxf(l, 0.0f) + log1pf(expf(-fabsf(l)));   // softplus
    float p = 1.0f / (1.0f + expf(-l));                    // sigmoid

    g_par[i] = fg ? i : -1;

    float4 v = make_float4(sp - l * y, p, p * y, y);
    v = blockReduceSum4(v);
    if (threadIdx.x == 0) {
        atomicAdd(&g_bce_sum, v.x);
        atomicAdd(&g_p_sum,   v.y);
        atomicAdd(&g_pt_sum,  v.z);
        atomicAdd(&g_t_sum,   v.w);
    }
    if (threadIdx.x < T1) atomicAdd(&g_cnt_t[threadIdx.x], sbins[threadIdx.x]);
}

// union over left & up edges (covers full 4-connectivity, per image)
__global__ void merge_kernel() {
    int i = blockIdx.x * blockDim.x + threadIdx.x;
    if (g_par[i] < 0) return;
    int w = i & (WW - 1);
    int h = (i >> 9) & (HH - 1);
    if (w > 0 && g_par[i - 1] >= 0)  uf_unite(i, i - 1);
    if (h > 0 && g_par[i - WW] >= 0) uf_unite(i, i - WW);
}

// flatten to root + compact roots: assign compact index, zero live rows
__global__ void compress_assign_kernel() {
    int i = blockIdx.x * blockDim.x + threadIdx.x;
    if (g_par[i] < 0) return;
    int r = uf_find(i);
    g_par[i] = r;
    if (r == i) {                              // this pixel is a component root
        int idx = atomicAdd(&g_m, 1);
        g_cidx[i] = idx;
        g_orig[idx] = i;
        g_cnt_c[idx] = 0;
        g_used[idx] = 0;
        #pragma unroll
        for (int t = 0; t < T1; t++) g_interc[(size_t)idx * T1 + t] = 0;
    }
}

// confusion counts into compact arrays
__global__ void build_kernel(const int* __restrict__ tgt) {
    int i = blockIdx.x * blockDim.x + threadIdx.x;
    int r = g_par[i];
    if (r >= 0) {
        int c = g_cidx[r];
        int t = tgt[i];
        atomicAdd(&g_interc[(size_t)c * T1 + t], 1);
        atomicAdd(&g_cnt_c[c], 1);
    }
}

// lexicographic argmin over (loss_bits, orig_root_id); loss > 0 so bits monotone
__global__ void argmin_kernel(int t) {
    int i = blockIdx.x * blockDim.x + threadIdx.x;
    int stride = gridDim.x * blockDim.x;
    int M = g_m;
    float ct = (float)g_cnt_t[t];
    unsigned long long best = ~0ULL;
    for (int c = i; c < M; c += stride) {
        if (!g_used[c]) {
            float cnt_p = (float)g_cnt_c[c];
            float it = (float)g_interc[(size_t)c * T1 + t];
            float bce = (NF * SP0F + cnt_p * C1F - it) / NF;
            float sum_pt = 0.5f * ct + C2F * it;
            float sum_p  = 0.5f * NF + C2F * cnt_p;
            float dice = 1.0f - (2.0f * sum_pt + 1.0f) / ((sum_p + ct) + 1.0f);
            float loss = bce + dice;
            unsigned long long key =
                ((unsigned long long)__float_as_uint(loss) << 32) | (unsigned)g_orig[c];
            best = (key < best) ? key : best;
        }
    }
    best = blockReduceMinU64(best);
    if (threadIdx.x == 0) atomicMin(&g_minkey, best);
}

__global__ void apply_kernel(int t) {
    int ct = g_cnt_t[t];
    unsigned long long key = g_minkey;
    bool present = ct > 0;
    bool any_avail = key != ~0ULL;
    if (present && any_avail) {
        g_acc += __uint_as_float((unsigned)(key >> 32));
        g_used[g_cidx[(unsigned)(key & 0xFFFFFFFFu)]] = 1;
        g_matched += 1.0f;
    } else if (present) {
        g_untgt += 1.0f;
    }
    g_minkey = ~0ULL;
}

__global__ void final_kernel(float* __restrict__ out) {
    float bce = g_bce_sum / NF;
    float dice = 1.0f - (2.0f * g_pt_sum + 1.0f) / ((g_p_sum + g_t_sum) + 1.0f);
    float res = bce + dice;
    out[0] = res + g_acc + ((float)g_m - g_matched) + g_untgt;
}

// ---------------- launch ----------------
extern "C" void kernel_launch(void* const* d_in, const int* in_sizes, int n_in,
                              void* d_out, int out_size) {
    const float* pred = (const float*)d_in[0];   // [4,2,512,512] f32
    const int*   tgt  = (const int*)d_in[1];     // [4,1,512,512] i32
    float* out = (float*)d_out;

    init_kernel<<<1, 32>>>();
    base_kernel<<<NPIX / 256, 256>>>(pred, tgt);
    merge_kernel<<<NPIX / 256, 256>>>();
    compress_assign_kernel<<<NPIX / 256, 256>>>();
    build_kernel<<<NPIX / 256, 256>>>(tgt);

    for (int t = 1; t < T1; t++) {
        argmin_kernel<<<256, 256>>>(t);
        apply_kernel<<<1, 1>>>(t);
    }
    final_kernel<<<1, 1>>>(out);
}